// round 17
// baseline (speedup 1.0000x reference)
#include <cuda_runtime.h>
#include <cuda_fp16.h>
#include <math.h>
#include <stdint.h>

#define E_CONST 320000
#define N_CONST 10000
typedef __half f16;

// ---------------- scratch (no allocations allowed) ----------------
static __device__ float    g_vff [(size_t)E_CONST * 64];   // fp32 [sincos48|dist16]
static __device__ float    g_hVW [N_CONST * 128];          // hV @ Wb1_top (fp32, per node)
static __device__ f16      g_hgh [N_CONST * 128];
static __device__ f16      g_w   [262144];                 // all weights, single fp16 plane, [n][k]
static __device__ float    g_sum [N_CONST * 4];
static __device__ float    g_hagg[N_CONST * 128];
static __device__ double   g_bnacc[32];
static __device__ float    g_bnst[32];

// weight plane offsets (elements)
#define OW_RED 0        // 256 x 320
#define OW_B1  81920    // 128 x 384
#define OW_B2  131072   // 128 x 128
#define OW_V1  147456   // 128 x 256
#define OW_V2  180224   // 128 x 128
#define OW_V3  196608   // 128 x 128
#define OW_O   212992   // 128 x 128
#define W_TOTAL 229376

// mega smem tail (beyond the 224KB working set)
#define ATT_OFF 229376
#define CEN_OFF 231424
#define SMEM_MEGA 231936

// ---------------- helpers ----------------
__device__ __forceinline__ uint32_t smem_u32(const void* p) {
    uint32_t a;
    asm("{ .reg .u64 t; cvta.to.shared.u64 t, %1; cvt.u32.u64 %0, t; }" : "=r"(a) : "l"(p));
    return a;
}
__device__ __forceinline__ void cp16(uint32_t dst, const void* src) {
    asm volatile("cp.async.cg.shared.global [%0], [%1], 16;"
        :: "r"(dst), "l"(__cvta_generic_to_global(src)) : "memory");
}
#define CP_COMMIT() asm volatile("cp.async.commit_group;" ::: "memory")
#define CP_WAIT(n)  asm volatile("cp.async.wait_group %0;" :: "n"(n) : "memory")

__device__ __forceinline__ void ldsm4(uint32_t* r, uint32_t addr) {
    asm volatile("ldmatrix.sync.aligned.m8n8.x4.shared.b16 {%0,%1,%2,%3}, [%4];"
        : "=r"(r[0]), "=r"(r[1]), "=r"(r[2]), "=r"(r[3]) : "r"(addr));
}
__device__ __forceinline__ void mmaf16(float* d, const uint32_t* a, const uint32_t* b) {
    asm volatile(
        "mma.sync.aligned.m16n8k16.row.col.f32.f16.f16.f32 "
        "{%0,%1,%2,%3}, {%4,%5,%6,%7}, {%8,%9}, {%0,%1,%2,%3};"
        : "+f"(d[0]), "+f"(d[1]), "+f"(d[2]), "+f"(d[3])
        : "r"(a[0]), "r"(a[1]), "r"(a[2]), "r"(a[3]), "r"(b[0]), "r"(b[1]));
}
__device__ __forceinline__ void red2(float* addr, float x, float y) {
    asm volatile("red.global.v2.f32.add [%0], {%1, %2};"
        :: "l"(__cvta_generic_to_global(addr)), "f"(x), "f"(y) : "memory");
}
__device__ __forceinline__ float gelu_f(float x) {
    return 0.5f * x * (1.f + erff(x * 0.70710678118654752f));
}
__device__ __forceinline__ uint32_t pack_h2(float a, float b) {
    __half2 hp; hp.x = __float2half_rn(a); hp.y = __float2half_rn(b);
    return reinterpret_cast<uint32_t&>(hp);
}

// ---------------- init ----------------
__global__ void init_kernel(float* gsum, float* hagg, double* bnacc, int N)
{
    int i = blockIdx.x * 256 + threadIdx.x;
    if (i < N * 128) hagg[i] = 0.f;
    if (i < N * 4) gsum[i] = 0.f;
    if (i < 32) bnacc[i] = 0.0;
}

// ---------------- geometry + BN stats ----------------
__global__ __launch_bounds__(256)
void geom_kernel(const int* __restrict__ eidx, const float* __restrict__ hvv,
                 const float* __restrict__ frame, const float* __restrict__ Wvec,
                 float* __restrict__ vff, double* __restrict__ bnacc, int E)
{
    extern __shared__ float sbuf[];   // 256 * 65 floats
    __shared__ float Ws[512];
    __shared__ float bsum[16], bsq[16];
    int tid = threadIdx.x;
    for (int i = tid; i < 512; i += 256) Ws[i] = Wvec[i];
    if (tid < 16) { bsum[tid] = 0.f; bsq[tid] = 0.f; }
    __syncthreads();

    const int e0 = blockIdx.x * 256;
    const int e = e0 + tid;
    float dloc[16];
#pragma unroll
    for (int o = 0; o < 16; o++) dloc[o] = 0.f;

    if (e < E) {
        const int c = eidx[e];
        const int d = eidx[E + e];
        float F[9];
#pragma unroll
        for (int i = 0; i < 9; i++) F[i] = frame[e * 9 + i];

        float vdt[48], vsrc[48];
        {
            const float4* pd = (const float4*)(hvv + (size_t)d * 48);
            const float4* pc = (const float4*)(hvv + (size_t)c * 48);
#pragma unroll
            for (int i = 0; i < 12; i++) {
                ((float4*)vdt)[i]  = pd[i];
                ((float4*)vsrc)[i] = pc[i];
            }
        }
#pragma unroll
        for (int v = 0; v < 16; v++) {
            const float x = vdt[v * 3 + 0], y = vdt[v * 3 + 1], z = vdt[v * 3 + 2];
            vdt[v * 3 + 0] = F[0] * x + F[1] * y + F[2] * z;
            vdt[v * 3 + 1] = F[3] * x + F[4] * y + F[5] * z;
            vdt[v * 3 + 2] = F[6] * x + F[7] * y + F[8] * z;
        }

        float* row = sbuf + tid * 65;
#pragma unroll
        for (int o = 0; o < 16; o++) {
            float v0 = vdt[o * 3 + 0], v1 = vdt[o * 3 + 1], v2 = vdt[o * 3 + 2];
#pragma unroll
            for (int v = 0; v < 16; v++) {
                const float wa = Ws[o * 32 + v], wb = Ws[o * 32 + 16 + v];
                v0 += wa * vdt[v * 3 + 0] + wb * vsrc[v * 3 + 0];
                v1 += wa * vdt[v * 3 + 1] + wb * vsrc[v * 3 + 1];
                v2 += wa * vdt[v * 3 + 2] + wb * vsrc[v * 3 + 2];
            }
            const float dist = sqrtf(v0 * v0 + v1 * v1 + v2 * v2) + 1e-6f;
            const float inv = 1.f / dist;
            row[o * 3 + 0] = v0 * inv;
            row[o * 3 + 1] = v1 * inv;
            row[o * 3 + 2] = v2 * inv;
            row[48 + o] = dist;
            dloc[o] = dist;
        }
    }

#pragma unroll
    for (int o = 0; o < 16; o++) {
        float v = dloc[o], v2 = v * v;
#pragma unroll
        for (int off = 16; off; off >>= 1) {
            v  += __shfl_down_sync(0xffffffffu, v, off);
            v2 += __shfl_down_sync(0xffffffffu, v2, off);
        }
        if ((tid & 31) == 0) { atomicAdd(&bsum[o], v); atomicAdd(&bsq[o], v2); }
    }
    __syncthreads();
    if (tid < 16) {
        atomicAdd(&bnacc[tid], (double)bsum[tid]);
        atomicAdd(&bnacc[16 + tid], (double)bsq[tid]);
    }

    const int nblk = (E - e0 < 256) ? (E - e0) : 256;
    for (int j = tid; j < nblk * 16; j += 256) {
        const int r = j >> 4, q = (j & 15) * 4;
        const float* sr = sbuf + r * 65 + q;
        *(float4*)(vff + (size_t)(e0 + r) * 64 + q) =
            make_float4(sr[0], sr[1], sr[2], sr[3]);
    }
}

__global__ void bn_finalize(const double* __restrict__ acc, const float* __restrict__ g,
                            const float* __restrict__ b, float* __restrict__ st, int E)
{
    int i = threadIdx.x;
    if (i >= 16) return;
    double mean = acc[i] / (double)E;
    double var  = acc[16 + i] / (double)E - mean * mean;
    float s = (float)((double)g[i] / sqrt(var + 1e-5));
    st[i] = s;
    st[16 + i] = b[i] - (float)mean * s;
}

// ---------------- conversion passes ----------------
__global__ void wprep_all(const float* __restrict__ W0, const float* __restrict__ W1,
                          const float* __restrict__ W2, const float* __restrict__ W3,
                          const float* __restrict__ W4, const float* __restrict__ W5,
                          const float* __restrict__ W6, f16* __restrict__ w)
{
    int idx = blockIdx.x * 256 + threadIdx.x;
    if (idx >= W_TOTAL) return;
    const float* src; int K, NT, start;
    if      (idx < OW_B1)  { src = W0; K = 320; NT = 256; start = OW_RED; }
    else if (idx < OW_B2)  { src = W1; K = 384; NT = 128; start = OW_B1; }
    else if (idx < OW_V1)  { src = W2; K = 128; NT = 128; start = OW_B2; }
    else if (idx < OW_V2)  { src = W3; K = 256; NT = 128; start = OW_V1; }
    else if (idx < OW_V3)  { src = W4; K = 128; NT = 128; start = OW_V2; }
    else if (idx < OW_O)   { src = W5; K = 128; NT = 128; start = OW_V3; }
    else                   { src = W6; K = 128; NT = 128; start = OW_O; }
    int local = idx - start;
    int k = local / NT, n = local % NT;
    w[start + (size_t)n * K + k] = __float2half_rn(src[local]);
}

// hVW = hV @ Wb1[0:128,:]  (exact fp32, per-node)
__global__ __launch_bounds__(256)
void hvw_kernel(const float* __restrict__ hV, const float* __restrict__ Wb1,
                float* __restrict__ hVW, int N)
{
    __shared__ float xs[2][128];
    const int t = threadIdx.x;
    const int which = t >> 7, c = t & 127;
    const int node = blockIdx.x * 2 + which;
    if (node < N) xs[which][c] = hV[(size_t)node * 128 + c];
    __syncthreads();
    if (node >= N) return;
    float s = 0.f;
#pragma unroll 8
    for (int k = 0; k < 128; k++) s += xs[which][k] * Wb1[k * 128 + c];
    hVW[(size_t)node * 128 + c] = s;
}

// hagg -> fp16 hi plane with softmax normalization folded in
__global__ void c2planes_norm(const float* __restrict__ x, const float* __restrict__ gsum,
                              f16* __restrict__ hi, int N)
{
    int i = blockIdx.x * 256 + threadIdx.x;
    if (i >= N * 128) return;
    int node = i >> 7, col = i & 127;
    float s = gsum[node * 4 + (col >> 5)];
    hi[i] = __float2half_rn(x[i] / (s > 0.f ? s : 1.f));
}

// ================= GEMM building blocks (512 threads, 16 warps = 4m x 4n) =================
template<int NT>
__device__ __forceinline__ void mma_half512(
    float (&acc)[2][NT][4], uint32_t aHi, uint32_t bB, int ks0, int tid)
{
    const int wid = tid >> 5, lane = tid & 31;
    const int wm = wid >> 2, wn = wid & 3;
    const int a_row = wm * 32 + (lane & 7) + ((lane & 8) ? 8 : 0);
    const int a_ub  = (lane & 16) ? 1 : 0;
    const int b_row0 = wn * (NT * 8) + (lane & 7) + ((lane & 16) ? 8 : 0);
    const int b_ub  = (lane & 8) ? 1 : 0;
#pragma unroll
    for (int kss = 0; kss < 2; kss++) {
        const int ks = ks0 + kss;
        uint32_t ahi[2][4];
#pragma unroll
        for (int mt = 0; mt < 2; mt++) {
            const int r = a_row + mt * 16;
            const int u = ks * 2 + a_ub;
            const uint32_t off = r * 128 + (uint32_t)(((u ^ (r & 7))) << 4);
            ldsm4(ahi[mt], aHi + off);
        }
        uint32_t bb[NT / 2][4];
#pragma unroll
        for (int g = 0; g < NT / 2; g++) {
            const int n = b_row0 + g * 16;
            const int u = ks * 2 + b_ub;
            const uint32_t off = n * 128 + (uint32_t)(((u ^ (n & 7))) << 4);
            ldsm4(bb[g], bB + off);
        }
#pragma unroll
        for (int mt = 0; mt < 2; mt++)
#pragma unroll
            for (int ntl = 0; ntl < NT; ntl++) {
                float* a_ = acc[mt][ntl];
                const uint32_t* bp = &bb[ntl >> 1][(ntl & 1) * 2];
                mmaf16(a_, ahi[mt], bp);
            }
    }
}

template<int NT>
__device__ __forceinline__ void mma_chunk(
    float (&acc)[2][NT][4], uint32_t aHi, uint32_t bB, int tid)
{
    mma_half512<NT>(acc, aHi, bB, 0, tid);
    mma_half512<NT>(acc, aHi, bB, 2, tid);
}

__device__ __forceinline__ void stage_w(uint32_t dst, const f16* __restrict__ W,
                                        int K, int k0, int rows, int tid)
{
    for (int i = tid; i < rows * 8; i += 512) {
        const int r = i >> 3, u = i & 7;
        const uint32_t d = r * 128 + (uint32_t)(((u ^ (r & 7))) << 4);
        cp16(dst + d, (const char*)(W + (size_t)r * K + k0) + u * 16);
    }
    CP_COMMIT();
}
__device__ __forceinline__ void stage_w2(uint32_t dst, const f16* __restrict__ W,
                                         int K, int k0, int tid)
{
    for (int i = tid; i < 2048; i += 512) {
        const int ch = i >> 10, rem = i & 1023;
        const int r = rem >> 3, u = rem & 7;
        const uint32_t d = ch * 16384 + r * 128 + (uint32_t)(((u ^ (r & 7))) << 4);
        cp16(dst + d, (const char*)(W + (size_t)r * K + k0 + ch * 64) + u * 16);
    }
    CP_COMMIT();
}
// stage a fused B pair: [W1 chunk (128 rows) | W2 chunk (128 rows)] -> 32KB at dst
__device__ __forceinline__ void stage_pair(uint32_t dst,
                                           const f16* __restrict__ W1, int K1, int k01,
                                           const f16* __restrict__ W2, int K2, int k02,
                                           int tid)
{
    for (int i = tid; i < 2048; i += 512) {
        const int half = i >> 10, rem = i & 1023;
        const int r = rem >> 3, u = rem & 7;
        const uint32_t d = half * 16384 + r * 128 + (uint32_t)(((u ^ (r & 7))) << 4);
        const f16* W = half ? W2 : W1;
        const int K = half ? K2 : K1;
        const int k0 = half ? k02 : k01;
        cp16(dst + d, (const char*)(W + (size_t)r * K + k0) + u * 16);
    }
    CP_COMMIT();
}

// store fragments -> smem fp16 hi plane (chunked layout), bias+activation
template<int NT, int ACT>
__device__ __forceinline__ void store_hi512(const float (&acc)[2][NT][4],
                                            char* smemp, uint32_t baseHi,
                                            const float* __restrict__ bias, int tid)
{
    const int wid = tid >> 5, lane = tid & 31;
    const int wm = wid >> 2, wn = wid & 3;
#pragma unroll
    for (int mt = 0; mt < 2; mt++)
#pragma unroll
        for (int nt = 0; nt < NT; nt++) {
            const int c = wn * (NT * 8) + nt * 8 + (lane & 3) * 2;
            const int kc = c >> 6, kk = c & 63, u = kk >> 3;
            const float b0 = bias ? bias[c] : 0.f;
            const float b1 = bias ? bias[c + 1] : 0.f;
#pragma unroll
            for (int half = 0; half < 2; half++) {
                const int r = wm * 32 + mt * 16 + (lane >> 2) + half * 8;
                float e0 = acc[mt][nt][half * 2] + b0;
                float e1 = acc[mt][nt][half * 2 + 1] + b1;
                if (ACT == 1) { e0 = fmaxf(e0, 0.f); e1 = fmaxf(e1, 0.f); }
                if (ACT == 2) { e0 = gelu_f(e0); e1 = gelu_f(e1); }
                const uint32_t ad = kc * 16384 + r * 128 +
                                    (uint32_t)(((u ^ (r & 7))) << 4) + (kk & 7) * 2;
                *(uint32_t*)(smemp + baseHi + ad) = pack_h2(e0, e1);
            }
        }
}

// ---------------- MEGA kernel (512 threads), all-fp16 single-product, fused x1|v1 ----------------
// smem: [0,64K) heHi (hE hi; later x2 fp32), [64K,128K) wbuf,
//       [128K,192K) xv (A-convert / x1+v1 hi / v2 hi), [192K,224K) stg, [224K..) att, cen
__global__ __launch_bounds__(512, 1)
void mega_kernel(const float* __restrict__ Vff, const float* __restrict__ HE,
                 const float* __restrict__ bn_st,
                 const float* __restrict__ hVW,
                 const int* __restrict__ eidx,
                 const f16* __restrict__ wred,
                 const f16* __restrict__ wb1, const float* __restrict__ bb1,
                 const f16* __restrict__ wb2, const float* __restrict__ bb2,
                 const float* __restrict__ Wb3, const float* __restrict__ bb3,
                 const f16* __restrict__ wv1, const float* __restrict__ bv1,
                 const f16* __restrict__ wv2, const float* __restrict__ bv2,
                 const f16* __restrict__ wv3, const float* __restrict__ bv3,
                 float* __restrict__ gsum, float* __restrict__ hagg, int M)
{
    extern __shared__ char smem[];
    const uint32_t sb = smem_u32(smem);
    const uint32_t heHi = sb;
    const uint32_t wbuf = sb + 65536;
    const uint32_t xv   = sb + 131072;
    const uint32_t stg  = sb + 196608;
    const int tid = threadIdx.x;
    const int wid = tid >> 5, lane = tid & 31;
    const int row0 = blockIdx.x * 128;

    const int lr = tid >> 2;
    const int arow = (row0 + lr < M) ? (row0 + lr) : (M - 1);
    const int cu0 = (tid & 3) * 4;

    {
        int* cens = (int*)(smem + CEN_OFF);
        if (tid < 128) {
            int er = row0 + tid;
            cens[tid] = eidx[er < M ? er : M - 1];
        }
    }

    // ================= P0: hE = [vff_bn | h_E] @ W_red (K=320, N=256) =================
    {
        float acc0[2][8][4];
#pragma unroll
        for (int i = 0; i < 2; i++)
#pragma unroll
            for (int j = 0; j < 8; j++)
#pragma unroll
                for (int q = 0; q < 4; q++) acc0[i][j][q] = 0.f;

        float4 areg[4];
        {
            const float4* pa = (const float4*)(Vff + (size_t)arow * 64);
#pragma unroll
            for (int jj = 0; jj < 4; jj++) areg[jj] = pa[cu0 + jj];
        }
        stage_w(xv + 32768, wred, 320, 0, 256, tid);   // B0 -> buf0

        for (int kc = 0; kc < 5; kc++) {
            {
                float4 f[4];
#pragma unroll
                for (int jj = 0; jj < 4; jj++) f[jj] = areg[jj];
                if (kc == 0 && cu0 >= 12) {
#pragma unroll
                    for (int jj = 0; jj < 4; jj++) {
                        const int u = cu0 + jj;
                        if (u >= 12) {
                            const int col = u * 4;
                            f[jj].x = fmaf(f[jj].x, bn_st[col - 48], bn_st[col - 32]);
                            f[jj].y = fmaf(f[jj].y, bn_st[col - 47], bn_st[col - 31]);
                            f[jj].z = fmaf(f[jj].z, bn_st[col - 46], bn_st[col - 30]);
                            f[jj].w = fmaf(f[jj].w, bn_st[col - 45], bn_st[col - 29]);
                        }
                    }
                }
#pragma unroll
                for (int jj = 0; jj < 2; jj++) {
                    uint32_t ph[4];
                    ph[0] = pack_h2(f[2*jj].x,   f[2*jj].y);
                    ph[1] = pack_h2(f[2*jj].z,   f[2*jj].w);
                    ph[2] = pack_h2(f[2*jj+1].x, f[2*jj+1].y);
                    ph[3] = pack_h2(f[2*jj+1].z, f[2*jj+1].w);
                    const int un = (cu0 >> 1) + jj;
                    const uint32_t ad = lr * 128 + (uint32_t)(((un ^ (lr & 7))) << 4);
                    *(uint4*)(smem + 131072 + ad) = make_uint4(ph[0], ph[1], ph[2], ph[3]);
                }
            }
            if (kc < 4) {
                const float4* pa = (const float4*)(HE + (size_t)arow * 256 + kc * 64);
#pragma unroll
                for (int jj = 0; jj < 4; jj++) areg[jj] = pa[cu0 + jj];
                stage_w(((kc + 1) & 1) ? stg : (xv + 32768), wred, 320, (kc + 1) * 64, 256, tid);
                CP_WAIT(1);
            } else {
                CP_WAIT(0);
            }
            __syncthreads();
            mma_chunk<8>(acc0, xv, (kc & 1) ? stg : (xv + 32768), tid);
            __syncthreads();
        }

        // prestage fused pairs [Wb1_bot[k] | Wv1[k]]: pair0,pair1 -> wbuf, pair2 -> stg
        stage_pair(wbuf,         wb1, 384, 128, wv1, 256, 0,   tid);  // GA1
        stage_pair(wbuf + 32768, wb1, 384, 192, wv1, 256, 64,  tid);  // GA2
        stage_pair(stg,          wb1, 384, 256, wv1, 256, 128, tid);  // G1
        store_hi512<8, 0>(acc0, smem, 0, nullptr, tid);               // hE hi -> heHi
    }
    CP_WAIT(1);                                          // GA1,GA2 done (G1 pending)
    __syncthreads();

    // ================= P1+P4 fused: [x1 | v1] = hE @ [Wb1_bot | Wv1], K=256, N=256 =================
    float acc1[2][8][4];
#pragma unroll
    for (int i = 0; i < 2; i++)
#pragma unroll
        for (int j = 0; j < 8; j++)
#pragma unroll
            for (int q = 0; q < 4; q++) acc1[i][j][q] = 0.f;
    {
        mma_chunk<8>(acc1, heHi, wbuf, tid);                      // k0 (pair0)
        __syncthreads();                                          // pair0 readers done
        stage_pair(wbuf, wb1, 384, 320, wv1, 256, 192, tid);      // G2: pair3 -> wbuf[0,32K)
        mma_chunk<8>(acc1, heHi + 16384, wbuf + 32768, tid);      // k1 (pair1)
        CP_WAIT(1);                                               // G1 done (G2 pending)
        __syncthreads();
        mma_chunk<8>(acc1, heHi + 32768, stg, tid);               // k2 (pair2)
        CP_WAIT(0);                                               // G2 done
        __syncthreads();
        mma_chunk<8>(acc1, heHi + 49152, wbuf, tid);              // k3 (pair3)
        __syncthreads();

        stage_w2(stg, wb2, 128, 0, tid);                          // G3: Wb2 -> stg

        // merged epilogue: cols 0-127 -> x1 (hVW+bias+relu), 128-255 -> v1 (bias+gelu)
        const int* cens = (const int*)(smem + CEN_OFF);
        const int wm = wid >> 2, wn = wid & 3;
#pragma unroll
        for (int mt = 0; mt < 2; mt++)
#pragma unroll
            for (int nt = 0; nt < 8; nt++) {
                const int c = wn * 64 + nt * 8 + (lane & 3) * 2;
#pragma unroll
                for (int half = 0; half < 2; half++) {
                    const int r = wm * 32 + mt * 16 + (lane >> 2) + half * 8;
                    float e0 = acc1[mt][nt][half * 2];
                    float e1 = acc1[mt][nt][half * 2 + 1];
                    if (c < 128) {
                        const float2 hv = *(const float2*)(hVW + (size_t)cens[r] * 128 + c);
                        e0 = fmaxf(e0 + bb1[c] + hv.x, 0.f);
                        e1 = fmaxf(e1 + bb1[c + 1] + hv.y, 0.f);
                        const int kc = c >> 6, kk = c & 63, u = kk >> 3;
                        const uint32_t ad = kc * 16384 + r * 128 +
                                            (uint32_t)(((u ^ (r & 7))) << 4) + (kk & 7) * 2;
                        *(uint32_t*)(smem + 131072 + ad) = pack_h2(e0, e1);
                    } else {
                        const int cv = c - 128;
                        e0 = gelu_f(e0 + bv1[cv]);
                        e1 = gelu_f(e1 + bv1[cv + 1]);
                        const int kc = cv >> 6, kk = cv & 63, u = kk >> 3;
                        const uint32_t ad = kc * 16384 + r * 128 +
                                            (uint32_t)(((u ^ (r & 7))) << 4) + (kk & 7) * 2;
                        *(uint32_t*)(smem + 163840 + ad) = pack_h2(e0, e1);
                    }
                }
            }
    }
    CP_WAIT(0);                                          // G3 done
    __syncthreads();

    // ================= P2: x2 = relu(x1 @ Wb2 + bb2) =================
    float acc2[2][4][4];
#pragma unroll
    for (int i = 0; i < 2; i++)
#pragma unroll
        for (int j = 0; j < 4; j++)
#pragma unroll
            for (int q = 0; q < 4; q++) acc2[i][j][q] = 0.f;
    mma_chunk<4>(acc2, xv,         stg,         tid);
    mma_chunk<4>(acc2, xv + 16384, stg + 16384, tid);
    __syncthreads();
    stage_w2(wbuf, wv2, 128, 0, tid);                    // G4: Wv2 -> wbuf[0,32K)
    // x2 fp32 -> heHi region (hE dead)
    {
        const int wm = wid >> 2, wn = wid & 3;
#pragma unroll
        for (int mt = 0; mt < 2; mt++)
#pragma unroll
            for (int nt = 0; nt < 4; nt++) {
                const int c = wn * 32 + nt * 8 + (lane & 3) * 2;
                const float b0 = bb2[c], b1 = bb2[c + 1];
#pragma unroll
                for (int half = 0; half < 2; half++) {
                    const int r = wm * 32 + mt * 16 + (lane >> 2) + half * 8;
                    float e0 = fmaxf(acc2[mt][nt][half * 2] + b0, 0.f);
                    float e1 = fmaxf(acc2[mt][nt][half * 2 + 1] + b1, 0.f);
                    *(float2*)(smem + ((size_t)r * 128 + c) * 4) = make_float2(e0, e1);
                }
            }
    }
    __syncthreads();

    // ================= P3: e = exp(logits), segment sum (Wb3 from L2) =================
    {
        const float* x2s = (const float*)smem;
        float* atts = (float*)(smem + ATT_OFF);
        const int* cens = (const int*)(smem + CEN_OFF);
        for (int rr = wid * 8; rr < wid * 8 + 8; rr++) {
            const int e = row0 + rr;
            if (e >= M) break;
            float p0 = 0.f, p1 = 0.f, p2 = 0.f, p3 = 0.f;
#pragma unroll
            for (int j = 0; j < 4; j++) {
                const int c = lane + j * 32;
                const float x = x2s[rr * 128 + c];
                const float4 w4 = *(const float4*)(Wb3 + c * 8);
                p0 += x * w4.x;
                p1 += x * w4.y;
                p2 += x * w4.z;
                p3 += x * w4.w;
            }
#pragma unroll
            for (int off = 16; off; off >>= 1) {
                p0 += __shfl_xor_sync(0xffffffffu, p0, off);
                p1 += __shfl_xor_sync(0xffffffffu, p1, off);
                p2 += __shfl_xor_sync(0xffffffffu, p2, off);
                p3 += __shfl_xor_sync(0xffffffffu, p3, off);
            }
            if (lane < 4) {
                const float p = (lane == 0) ? p0 : (lane == 1) ? p1 : (lane == 2) ? p2 : p3;
                const float l = (p + bb3[lane]) * 0.17677669529663687f;
                const float ex = expf(l);
                atts[rr * 4 + lane] = ex;
                atomicAdd(&gsum[cens[rr] * 4 + lane], ex);
            }
        }
    }
    CP_WAIT(0);                                          // G4 done (hidden behind store + P3)
    __syncthreads();

    // ================= P5: v2 = gelu(v1 @ Wv2 + bv2) =================
    float acc4[2][4][4];
#pragma unroll
    for (int i = 0; i < 2; i++)
#pragma unroll
        for (int j = 0; j < 4; j++)
#pragma unroll
            for (int q = 0; q < 4; q++) acc4[i][j][q] = 0.f;
    mma_chunk<4>(acc4, xv + 32768, wbuf,         tid);
    mma_chunk<4>(acc4, xv + 49152, wbuf + 16384, tid);
    __syncthreads();
    stage_w2(stg, wv3, 128, 0, tid);                     // G5: Wv3 -> stg
    store_hi512<4, 2>(acc4, smem, 131072, bv2, tid);     // v2 hi -> xv[0,32K) (x1 dead)
    CP_WAIT(0);
    __syncthreads();

    // ================= P6: V = v2 @ Wv3 + bv3; hagg[center] += e * V =================
    float acc5[2][4][4];
#pragma unroll
    for (int i = 0; i < 2; i++)
#pragma unroll
        for (int j = 0; j < 4; j++)
#pragma unroll
            for (int q = 0; q < 4; q++) acc5[i][j][q] = 0.f;
    mma_chunk<4>(acc5, xv,         stg,         tid);
    mma_chunk<4>(acc5, xv + 16384, stg + 16384, tid);
    {
        const float* atts = (const float*)(smem + ATT_OFF);
        const int* cens = (const int*)(smem + CEN_OFF);
        const int wm = wid >> 2, wn = wid & 3;
#pragma unroll
        for (int mt = 0; mt < 2; mt++) {
#pragma unroll
            for (int nt = 0; nt < 4; nt++) {
                const int c = wn * 32 + nt * 8 + (lane & 3) * 2;
                const int h = c >> 5;
                const float b0 = bv3[c], b1 = bv3[c + 1];
#pragma unroll
                for (int half = 0; half < 2; half++) {
                    const int rl = wm * 32 + mt * 16 + (lane >> 2) + half * 8;
                    if (row0 + rl < M) {
                        const float a = atts[rl * 4 + h];
                        float* dst = hagg + (size_t)cens[rl] * 128 + c;
                        red2(dst, (acc5[mt][nt][half * 2] + b0) * a,
                                  (acc5[mt][nt][half * 2 + 1] + b1) * a);
                    }
                }
            }
        }
    }
}

// ---------------- standalone GEMM (W_O), 256 threads, single fp16 ----------------
__global__ __launch_bounds__(256, 1)
void hmma_gemm_o(const f16* __restrict__ A, const f16* __restrict__ B,
                 float* __restrict__ Cf, int M)
{
    extern __shared__ char smem[];
    const uint32_t sb = smem_u32(smem);
    const int tid = threadIdx.x;
    const int wid = tid >> 5, lane = tid & 31;
    const int row0 = blockIdx.x * 128;

    const int lr = tid >> 1;
    const int arow = (row0 + lr < M) ? (row0 + lr) : (M - 1);

    float acc[2][8][4];
#pragma unroll
    for (int i = 0; i < 2; i++)
#pragma unroll
        for (int j = 0; j < 8; j++)
#pragma unroll
            for (int q = 0; q < 4; q++) acc[i][j][q] = 0.f;

    const int wm = wid >> 1, wn = wid & 1;
    const int a_row = wm * 32 + (lane & 7) + ((lane & 8) ? 8 : 0);
    const int a_ub  = (lane & 16) ? 1 : 0;
    const int b_row0 = wn * 64 + (lane & 7) + ((lane & 16) ? 8 : 0);
    const int b_ub  = (lane & 8) ? 1 : 0;

    for (int kc = 0; kc < 2; kc++) {
        const int k0 = kc * 64;
#pragma unroll
        for (int i = 0; i < 4; i++) {
            const int u = (tid & 1) * 4 + i;
            const uint32_t d = lr * 128 + (uint32_t)(((u ^ (lr & 7))) << 4);
            cp16(sb + d, (const char*)(A + (size_t)arow * 128 + k0) + u * 16);
        }
        for (int i = tid; i < 128 * 8; i += 256) {
            const int r = i >> 3, u = i & 7;
            const uint32_t d = r * 128 + (uint32_t)(((u ^ (r & 7))) << 4);
            cp16(sb + 16384 + d, (const char*)(B + (size_t)r * 128 + k0) + u * 16);
        }
        CP_COMMIT();
        CP_WAIT(0);
        __syncthreads();
#pragma unroll
        for (int ks = 0; ks < 4; ks++) {
            uint32_t ahi[2][4];
#pragma unroll
            for (int mt = 0; mt < 2; mt++) {
                const int r = a_row + mt * 16;
                const int u = ks * 2 + a_ub;
                const uint32_t off = r * 128 + (uint32_t)(((u ^ (r & 7))) << 4);
                ldsm4(ahi[mt], sb + off);
            }
            uint32_t bb[4][4];
#pragma unroll
            for (int g = 0; g < 4; g++) {
                const int n = b_row0 + g * 16;
                const int u = ks * 2 + b_ub;
                const uint32_t off = n * 128 + (uint32_t)(((u ^ (n & 7))) << 4);
                ldsm4(bb[g], sb + 16384 + off);
            }
#pragma unroll
            for (int mt = 0; mt < 2; mt++)
#pragma unroll
                for (int ntl = 0; ntl < 8; ntl++) {
                    float* a_ = acc[mt][ntl];
                    const uint32_t* bp = &bb[ntl >> 1][(ntl & 1) * 2];
                    mmaf16(a_, ahi[mt], bp);
                }
        }
        __syncthreads();
    }

#pragma unroll
    for (int mt = 0; mt < 2; mt++) {
        const int r = row0 + wm * 32 + mt * 16 + (lane >> 2);
#pragma unroll
        for (int nt = 0; nt < 8; nt++) {
            const int c = wn * 64 + nt * 8 + (lane & 3) * 2;
#pragma unroll
            for (int half = 0; half < 2; half++) {
                const int rr = r + half * 8;
                if (rr >= M) continue;
                *(float2*)(Cf + (size_t)rr * 128 + c) =
                    make_float2(acc[mt][nt][half * 2], acc[mt][nt][half * 2 + 1]);
            }
        }
    }
}

// ---------------- host launch ----------------
extern "C" void kernel_launch(void* const* d_in, const int* in_sizes, int n_in,
                              void* d_out, int out_size)
{
    const float* h_V   = (const float*)d_in[0];
    const float* h_E   = (const float*)d_in[1];
    const int*   eidx  = (const int*)  d_in[2];
    const float* hvv   = (const float*)d_in[3];
    const float* frame = (const float*)d_in[4];
    const float* W_vec = (const float*)d_in[5];
    const float* W_red = (const float*)d_in[6];
    const float* Wb1   = (const float*)d_in[7];
    const float* bb1   = (const float*)d_in[8];
    const float* Wb2   = (const float*)d_in[9];
    const float* bb2   = (const float*)d_in[10];
    const float* Wb3   = (const float*)d_in[11];
    const float* bb3   = (const float*)d_in[12];
    const float* Wv1   = (const float*)d_in[13];
    const float* bv1   = (const float*)d_in[14];
    const float* Wv2   = (const float*)d_in[15];
    const float* bv2   = (const float*)d_in[16];
    const float* Wv3   = (const float*)d_in[17];
    const float* bv3   = (const float*)d_in[18];
    const float* W_O   = (const float*)d_in[19];
    const float* bn_g  = (const float*)d_in[20];
    const float* bn_b  = (const float*)d_in[21];

    int E = in_sizes[2] / 2;
    int N = in_sizes[0] / 128;
    float* out = (float*)d_out;

    float *vff, *hVW, *gsum, *hagg, *bnst;
    f16 *hgh, *w;
    double* bnacc;
    cudaGetSymbolAddress((void**)&vff,   g_vff);
    cudaGetSymbolAddress((void**)&hVW,   g_hVW);
    cudaGetSymbolAddress((void**)&hgh,   g_hgh);
    cudaGetSymbolAddress((void**)&w,     g_w);
    cudaGetSymbolAddress((void**)&gsum,  g_sum);
    cudaGetSymbolAddress((void**)&hagg,  g_hagg);
    cudaGetSymbolAddress((void**)&bnacc, g_bnacc);
    cudaGetSymbolAddress((void**)&bnst,  g_bnst);

    const int SMEM_O = 32768;
    const int SMEM_G = 256 * 65 * 4;   // 66560
    cudaFuncSetAttribute(mega_kernel, cudaFuncAttributeMaxDynamicSharedMemorySize, SMEM_MEGA);
    cudaFuncSetAttribute(hmma_gemm_o, cudaFuncAttributeMaxDynamicSharedMemorySize, SMEM_O);
    cudaFuncSetAttribute(geom_kernel, cudaFuncAttributeMaxDynamicSharedMemorySize, SMEM_G);

    int Mt = (E + 127) / 128;
    int Mo = (N + 127) / 128;

    init_kernel<<<(N * 128 + 255) / 256, 256>>>(gsum, hagg, bnacc, N);
    geom_kernel<<<(E + 255) / 256, 256, SMEM_G>>>(eidx, hvv, frame, W_vec, vff, bnacc, E);
    bn_finalize<<<1, 32>>>(bnacc, bn_g, bn_b, bnst, E);

    wprep_all<<<(W_TOTAL + 255) / 256, 256>>>(W_red, Wb1, Wb2, Wv1, Wv2, Wv3, W_O, w);
    hvw_kernel<<<(N + 1) / 2, 256>>>(h_V, Wb1, hVW, N);

    mega_kernel<<<Mt, 512, SMEM_MEGA>>>(
        vff, h_E, bnst, hVW, eidx,
        w + OW_RED,
        w + OW_B1, bb1,
        w + OW_B2, bb2,
        Wb3, bb3,
        w + OW_V1, bv1,
        w + OW_V2, bv2,
        w + OW_V3, bv3,
        gsum, hagg, E);

    c2planes_norm<<<(N * 128 + 255) / 256, 256>>>(hagg, gsum, hgh, N);
    hmma_gemm_o<<<Mo, 256, SMEM_O>>>(hgh, w + OW_O, out, N);
}